// round 5
// baseline (speedup 1.0000x reference)
#include <cuda_runtime.h>
#include <cuda_bf16.h>

// Problem constants
#define B_    8
#define TOUT  256
#define TIN   512
#define L_    128
#define DIN   128
#define DATT  128
// out tensor: (8,256,256) then h (8,128) then c (8,128)
#define OUT_MAIN  (B_*TOUT*(L_+DATT))      // 524288
#define OUT_H_OFF OUT_MAIN                 // 524288
#define OUT_C_OFF (OUT_MAIN + B_*L_)       // 525312

// LSTM: K-packed FFMA2. Rows 0..95 in registers (48 k-pairs x 2 cols),
// rows 96..127 in SMEM as k-pair u64s, grouped as ulonglong2 (4 rows/load).
#define RPAIRS 48            // register k-pairs per column (rows 0..95)
#define SCHUNK 8             // SMEM 4-row chunks (rows 96..127)
// dyn smem: wsp2[8][512] ulonglong2 (64KB) + h_s[128] f32 + z_s[512] f32
#define LSTM_DYN_SMEM (SCHUNK*512*16 + 128*4 + 512*4)   // 68096 B

// Device scratch (no cudaMalloc allowed)
__device__ float g_keys[B_ * TIN * L_];     // (8,512,128) 2MB
__device__ float g_xz  [B_ * TOUT * 4*L_];  // (8,256,512) 2MB
__device__ float g_q   [B_ * TOUT * L_];    // (8,256,128) 1MB

typedef unsigned long long u64;

__device__ __forceinline__ u64 ffma2(u64 a, u64 b, u64 c) {
    u64 d;
    asm("fma.rn.f32x2 %0, %1, %2, %3;" : "=l"(d) : "l"(a), "l"(b), "l"(c));
    return d;
}
__device__ __forceinline__ u64 add2(u64 a, u64 b) {
    u64 d;
    asm("add.rn.f32x2 %0, %1, %2;" : "=l"(d) : "l"(a), "l"(b));
    return d;
}
__device__ __forceinline__ u64 pack2(float lo, float hi) {
    u64 d;
    asm("mov.b64 %0, {%1, %2};" : "=l"(d) : "f"(lo), "f"(hi));
    return d;
}
__device__ __forceinline__ float2 unpack2(u64 v) {
    float2 r;
    asm("mov.b64 {%0, %1}, %2;" : "=f"(r.x), "=f"(r.y) : "l"(v));
    return r;
}

__device__ __forceinline__ float tanh_fast(float x) {
    float y;
    asm("tanh.approx.f32 %0, %1;" : "=f"(y) : "f"(x));
    return y;
}
__device__ __forceinline__ float sigmoidf_(float x) {
    return 1.0f / (1.0f + __expf(-x));
}

// ---------------------------------------------------------------------------
// Generic small GEMM: C[M,N] = A[M,K=128] @ W[K,N] + bias[N]
// A row stride = lda. Block: 128 threads, each computes 16 rows x 1 column.
// grid = (M/16, N/128).
// ---------------------------------------------------------------------------
__global__ __launch_bounds__(128)
void gemm_bias_kernel(const float* __restrict__ A, int lda,
                      const float* __restrict__ W,
                      const float* __restrict__ bias,
                      float* __restrict__ C, int N)
{
    const int K = 128;
    const int ROWS = 16;
    __shared__ float As[ROWS][K];   // 8KB

    const int row0 = blockIdx.x * ROWS;
    const int col  = blockIdx.y * 128 + threadIdx.x;

    for (int i = threadIdx.x; i < ROWS * (K / 4); i += 128) {
        int r  = i >> 5;
        int c4 = i & 31;
        ((float4*)As[r])[c4] = ((const float4*)(A + (size_t)(row0 + r) * lda))[c4];
    }
    __syncthreads();

    float acc[ROWS];
#pragma unroll
    for (int r = 0; r < ROWS; r++) acc[r] = 0.f;

#pragma unroll 4
    for (int k = 0; k < K; k++) {
        float w = W[(size_t)k * N + col];
#pragma unroll
        for (int r = 0; r < ROWS; r++)
            acc[r] = fmaf(As[r][k], w, acc[r]);
    }

    const float bb = bias[col];
#pragma unroll
    for (int r = 0; r < ROWS; r++)
        C[(size_t)(row0 + r) * N + col] = acc[r] + bb;
}

// ---------------------------------------------------------------------------
// LSTM scan v5: one block per batch, 256 threads. Thread j owns gate columns
// j and j+256. K-PACKED FFMA2: each FFMA2 accumulates rows (k,k+1) for one
// column; the h operand (h_k, h_{k+1}) comes straight from a plain float
// h array (no duplication), so one broadcast LDS.128 feeds 4 rows.
//  - Wr rows 0..95: registers, 48 k-pairs x 2 cols = 192 regs/thread
//  - Wr rows 96..127: SMEM ulonglong2 (2 k-pairs = 4 rows), conflict-free
//  - z_j = lo+hi of packed accumulator
// Per-step model: FMA pipe 512 cyc, LSU ~768 wavefronts.
// ---------------------------------------------------------------------------
__global__ __launch_bounds__(256, 1)
void lstm_kernel(const float* __restrict__ xz,
                 const float* __restrict__ Wr,   // (128, 512) row-major
                 float* __restrict__ out)
{
    extern __shared__ u64 smraw[];
    ulonglong2* wsp2 = (ulonglong2*)smraw;            // [SCHUNK][512]
    float* h_s = (float*)(wsp2 + SCHUNK * 512);       // [128], 16B aligned
    float* z_s = h_s + 128;                           // [512]

    const int b = blockIdx.x;
    const int j = threadIdx.x;     // 0..255

    // Register weights: k-pairs for rows 0..95, columns j and j+256
    u64 w0[RPAIRS], w1[RPAIRS];
#pragma unroll
    for (int p = 0; p < RPAIRS; p++) {
        w0[p] = pack2(Wr[(2 * p) * 512 + j],       Wr[(2 * p + 1) * 512 + j]);
        w1[p] = pack2(Wr[(2 * p) * 512 + j + 256], Wr[(2 * p + 1) * 512 + j + 256]);
    }

    // SMEM weights rows 96..127: chunk q covers rows 96+4q .. 96+4q+3
    for (int i = j; i < SCHUNK * 512; i += 256) {
        int q = i >> 9, col = i & 511;
        int r0 = 96 + 4 * q;
        ulonglong2 v;
        v.x = pack2(Wr[(r0 + 0) * 512 + col], Wr[(r0 + 1) * 512 + col]);
        v.y = pack2(Wr[(r0 + 2) * 512 + col], Wr[(r0 + 3) * 512 + col]);
        wsp2[q * 512 + col] = v;
    }

    float c = 0.f;
    if (j < L_) h_s[j] = 0.f;
    __syncthreads();

    const float* xzb = xz + (size_t)b * TOUT * 512;

    float x0 = xzb[j];
    float x1 = xzb[j + 256];

    for (int t = 0; t < TOUT; t++) {
        u64 a0 = pack2(x0, 0.f);   // col j   accumulator (even-k lo, odd-k hi)
        u64 a1 = 0ull;
        u64 a2 = pack2(x1, 0.f);   // col j+256 accumulator
        u64 a3 = 0ull;

        // prefetch next step's xz (independent of the FMA chain below)
        float x0n = 0.f, x1n = 0.f;
        if (t + 1 < TOUT) {
            x0n = xzb[(t + 1) * 512 + j];
            x1n = xzb[(t + 1) * 512 + j + 256];
        }

        // rows 0..95: register weights; 1 broadcast LDS.128 -> 4 rows x 2 cols
#pragma unroll
        for (int i = 0; i < RPAIRS / 2; i++) {          // i = 0..23
            ulonglong2 hp = *(const ulonglong2*)&h_s[4 * i];
            a0 = ffma2(hp.x, w0[2 * i],     a0);
            a1 = ffma2(hp.y, w0[2 * i + 1], a1);
            a2 = ffma2(hp.x, w1[2 * i],     a2);
            a3 = ffma2(hp.y, w1[2 * i + 1], a3);
        }
        // rows 96..127: SMEM weights (LDS.128, 16B stride across threads)
#pragma unroll
        for (int q = 0; q < SCHUNK; q++) {
            ulonglong2 hp = *(const ulonglong2*)&h_s[96 + 4 * q];
            ulonglong2 wa = wsp2[q * 512 + j];
            ulonglong2 wb = wsp2[q * 512 + j + 256];
            a0 = ffma2(hp.x, wa.x, a0);
            a1 = ffma2(hp.y, wa.y, a1);
            a2 = ffma2(hp.x, wb.x, a2);
            a3 = ffma2(hp.y, wb.y, a3);
        }
        {
            float2 f0 = unpack2(add2(a0, a1));
            float2 f1 = unpack2(add2(a2, a3));
            z_s[j]       = f0.x + f0.y;
            z_s[j + 256] = f1.x + f1.y;
        }
        __syncthreads();

        if (j < L_) {
            const float zi = z_s[j];
            const float zf = z_s[j + 128];
            const float zg = z_s[j + 256];
            const float zo = z_s[j + 384];
            const float ig = sigmoidf_(zi);
            const float fg = sigmoidf_(zf);
            const float gg = tanhf(zg);          // precise: recurrence-critical
            const float og = sigmoidf_(zo);
            c = fmaf(fg, c, ig * gg);
            const float hn = og * tanhf(c);
            h_s[j] = hn;
            out[((size_t)(b * TOUT + t)) * 256 + j] = hn;
        }
        __syncthreads();

        x0 = x0n;
        x1 = x1n;
    }

    if (j < L_) {
        out[OUT_H_OFF + b * L_ + j] = h_s[j];
        out[OUT_C_OFF + b * L_ + j] = c;
    }
}

// ---------------------------------------------------------------------------
// Fused Bahdanau attention: scores = tanh(keys + q) . W3 -> softmax -> @ att.
// Block = (b, 8 q-rows), 256 threads (8 warps, warp w owns q-row w).
// Never materializes the (8,256,512,128) tensor. MUFU(tanh)-bound by model
// (~134M tanh @ 0.5 MUFU-instr/cyc/SM over 148 SMs ~= 33 us).
// ---------------------------------------------------------------------------
__global__ __launch_bounds__(256)
void attn_kernel(const float* __restrict__ keys,   // (8,512,128)
                 const float* __restrict__ q,      // (8,256,128)
                 const float* __restrict__ att,    // (8,512,128)
                 const float* __restrict__ W3,     // (128,)
                 float* __restrict__ out)
{
    const int b    = blockIdx.y;
    const int q0   = blockIdx.x * 8;
    const int tid  = threadIdx.x;
    const int warp = tid >> 5;
    const int lane = tid & 31;

    __shared__ float q_s[8][L_];
    __shared__ float w3_s[L_];
    __shared__ float p_s[8][TIN];

    for (int i = tid; i < 8 * L_; i += 256) {
        int r = i >> 7, l = i & 127;
        q_s[r][l] = q[((size_t)(b * TOUT + q0 + r)) * L_ + l];
    }
    if (tid < L_) w3_s[tid] = W3[tid];
    __syncthreads();

    const float* keysb = keys + (size_t)b * TIN * L_;
    const float* attb  = att  + (size_t)b * TIN * L_;

    // ---- Phase 1: scores. warp w -> q-row w, all k. lane owns l = lane*4..+3
    {
        const int r = warp;
        const float4 qv = *(const float4*)&q_s[r][lane * 4];
        const float4 wv = *(const float4*)&w3_s[lane * 4];
#pragma unroll 2
        for (int k = 0; k < TIN; k++) {
            float4 kr = *(const float4*)(keysb + (size_t)k * L_ + lane * 4);
            float s;
            s = tanh_fast(kr.x + qv.x) * wv.x;
            s = fmaf(tanh_fast(kr.y + qv.y), wv.y, s);
            s = fmaf(tanh_fast(kr.z + qv.z), wv.z, s);
            s = fmaf(tanh_fast(kr.w + qv.w), wv.w, s);
#pragma unroll
            for (int o = 16; o; o >>= 1)
                s += __shfl_xor_sync(0xffffffffu, s, o);
            if (lane == 0) p_s[r][k] = s;   // b3 shift-invariant under softmax
        }
    }
    __syncthreads();

    // ---- Phase 2: softmax per q-row (warp-parallel over k)
    {
        const int r = warp;
        float mx = -1e30f;
        for (int k = lane; k < TIN; k += 32) mx = fmaxf(mx, p_s[r][k]);
#pragma unroll
        for (int o = 16; o; o >>= 1)
            mx = fmaxf(mx, __shfl_xor_sync(0xffffffffu, mx, o));
        float sum = 0.f;
        for (int k = lane; k < TIN; k += 32) {
            float e = __expf(p_s[r][k] - mx);
            p_s[r][k] = e;
            sum += e;
        }
#pragma unroll
        for (int o = 16; o; o >>= 1)
            sum += __shfl_xor_sync(0xffffffffu, sum, o);
        float inv = 1.0f / sum;
        for (int k = lane; k < TIN; k += 32) p_s[r][k] *= inv;
    }
    __syncthreads();

    // ---- Phase 3: weighted = attn @ att. warp w -> q-row w, lane owns d=lane*4..+3
    {
        const int r = warp;
        float4 acc = make_float4(0.f, 0.f, 0.f, 0.f);
#pragma unroll 2
        for (int k = 0; k < TIN; k++) {
            float  p = p_s[r][k];
            float4 a = *(const float4*)(attb + (size_t)k * L_ + lane * 4);
            acc.x = fmaf(p, a.x, acc.x);
            acc.y = fmaf(p, a.y, acc.y);
            acc.z = fmaf(p, a.z, acc.z);
            acc.w = fmaf(p, a.w, acc.w);
        }
        float* op = out + ((size_t)(b * TOUT + q0 + r)) * 256 + 128 + lane * 4;
        *(float4*)op = acc;
    }
}

// ---------------------------------------------------------------------------
extern "C" void kernel_launch(void* const* d_in, const int* in_sizes, int n_in,
                              void* d_out, int out_size)
{
    const float* inputs   = (const float*)d_in[0];   // (8,256,128)
    const float* attended = (const float*)d_in[1];   // (8,512,128)
    const float* lstm_k   = (const float*)d_in[2];   // (128,512)
    const float* lstm_rk  = (const float*)d_in[3];   // (128,512)
    const float* lstm_b   = (const float*)d_in[4];   // (512,)
    const float* W1       = (const float*)d_in[5];   // (128,128)
    const float* b1       = (const float*)d_in[6];   // (128,)
    const float* W2       = (const float*)d_in[7];   // (128,128)
    const float* b2       = (const float*)d_in[8];   // (128,)
    const float* W3       = (const float*)d_in[9];   // (128,1)
    // d_in[10] = b3: shift-invariant under softmax, unused

    float* out = (float*)d_out;

    float* keys; cudaGetSymbolAddress((void**)&keys, g_keys);
    float* xz;   cudaGetSymbolAddress((void**)&xz,   g_xz);
    float* qbuf; cudaGetSymbolAddress((void**)&qbuf, g_q);

    // Opt-in to >48KB dynamic SMEM for the LSTM kernel (config, not allocation)
    cudaFuncSetAttribute(lstm_kernel,
                         cudaFuncAttributeMaxDynamicSharedMemorySize,
                         LSTM_DYN_SMEM);

    // keys = attended @ W1 + b1     : M=4096, N=128  (independent of LSTM)
    {
        dim3 grid(B_ * TIN / 16, 1);
        gemm_bias_kernel<<<grid, 128>>>(attended, 128, W1, b1, keys, 128);
    }
    // xz = inputs @ lstm_kernel + lstm_bias : M=2048, N=512
    {
        dim3 grid(B_ * TOUT / 16, 4);
        gemm_bias_kernel<<<grid, 128>>>(inputs, 128, lstm_k, lstm_b, xz, 512);
    }
    // LSTM scan (sequential over t). Writes x into out[...,0:128] and h,c tail.
    lstm_kernel<<<B_, 256, LSTM_DYN_SMEM>>>(xz, lstm_rk, out);

    // q = x @ W2 + b2 (x read from strided out buffer, lda=256) : M=2048, N=128
    {
        dim3 grid(B_ * TOUT / 16, 1);
        gemm_bias_kernel<<<grid, 128>>>(out, 256, W2, b2, qbuf, 128);
    }
    // fused scores -> softmax -> weighted, writes out[...,128:256]
    {
        dim3 grid(TOUT / 8, B_);
        attn_kernel<<<grid, 256>>>(keys, qbuf, attended, W3, out);
    }
}

// round 13
// speedup vs baseline: 1.1244x; 1.1244x over previous
#include <cuda_runtime.h>
#include <cuda_bf16.h>

// Problem constants
#define B_    8
#define TOUT  256
#define TIN   512
#define L_    128
#define DIN   128
#define DATT  128
// out tensor: (8,256,256) then h (8,128) then c (8,128)
#define OUT_MAIN  (B_*TOUT*(L_+DATT))      // 524288
#define OUT_H_OFF OUT_MAIN                 // 524288
#define OUT_C_OFF (OUT_MAIN + B_*L_)       // 525312

// LSTM: K-packed FFMA2. Rows 0..95 in registers (48 k-pairs x 2 cols),
// rows 96..127 in SMEM as k-pair u64s, grouped as ulonglong2 (4 rows/load).
#define RPAIRS 48            // register k-pairs per column (rows 0..95)
#define SCHUNK 8             // SMEM 4-row chunks (rows 96..127)
// dyn smem: wsp2[8][512] ulonglong2 (64KB) + h_s[128] f32 + zfo_s[128] f32x2
#define LSTM_DYN_SMEM (SCHUNK*512*16 + 128*4 + 128*8)   // 67072 B

// keys-GEMM piggyback blocks inside the lstm launch
#define KEYS_ROWS   16
#define KEYS_BLOCKS (B_ * TIN / KEYS_ROWS)   // 256

// Attention dyn smem (floats): w2s[16384] (aliased by p_s[8][512] later)
// + qs[1024] + xs[1024] + w3s[128] + b2s[128]
#define ATTN_SMEM_FLOATS (16384 + 1024 + 1024 + 128 + 128)
#define ATTN_DYN_SMEM (ATTN_SMEM_FLOATS * 4)             // 74752 B

// Device scratch (no cudaMalloc allowed)
__device__ float g_keys[B_ * TIN * L_];     // (8,512,128) 2MB
__device__ float g_xz  [B_ * TOUT * 4*L_];  // (8,256,512) 2MB

typedef unsigned long long u64;

__device__ __forceinline__ u64 ffma2(u64 a, u64 b, u64 c) {
    u64 d;
    asm("fma.rn.f32x2 %0, %1, %2, %3;" : "=l"(d) : "l"(a), "l"(b), "l"(c));
    return d;
}
__device__ __forceinline__ u64 add2(u64 a, u64 b) {
    u64 d;
    asm("add.rn.f32x2 %0, %1, %2;" : "=l"(d) : "l"(a), "l"(b));
    return d;
}
__device__ __forceinline__ u64 pack2(float lo, float hi) {
    u64 d;
    asm("mov.b64 %0, {%1, %2};" : "=l"(d) : "f"(lo), "f"(hi));
    return d;
}
__device__ __forceinline__ float2 unpack2(u64 v) {
    float2 r;
    asm("mov.b64 {%0, %1}, %2;" : "=f"(r.x), "=f"(r.y) : "l"(v));
    return r;
}

__device__ __forceinline__ float tanh_fast(float x) {
    float y;
    asm("tanh.approx.f32 %0, %1;" : "=f"(y) : "f"(x));
    return y;
}
// Accurate-enough fast tanh: rel err ~1e-6 (vs tanh.approx ~5e-4).
// exp overflow -> inf -> 2/inf = 0 -> returns 1; exp underflow -> returns -1.
__device__ __forceinline__ float tanh_e(float x) {
    float e = __expf(2.0f * x);
    return 1.0f - __fdividef(2.0f, e + 1.0f);
}
__device__ __forceinline__ float sigmoidf_(float x) {
    return __fdividef(1.0f, 1.0f + __expf(-x));
}

// ---------------------------------------------------------------------------
// Generic small GEMM: C[M,N] = A[M,K=128] @ W[K,N] + bias[N]
// Block: 128 threads, each computes 8 rows x 1 column. grid = (M/8, N/128).
// High block count to hide L2 latency (v5 profile: occ 6.2%, latency-bound).
// ---------------------------------------------------------------------------
__global__ __launch_bounds__(128)
void gemm_bias_kernel(const float* __restrict__ A, int lda,
                      const float* __restrict__ W,
                      const float* __restrict__ bias,
                      float* __restrict__ C, int N)
{
    const int K = 128;
    const int ROWS = 8;
    __shared__ float As[ROWS][K];   // 4KB

    const int row0 = blockIdx.x * ROWS;
    const int col  = blockIdx.y * 128 + threadIdx.x;

    for (int i = threadIdx.x; i < ROWS * (K / 4); i += 128) {
        int r  = i >> 5;
        int c4 = i & 31;
        ((float4*)As[r])[c4] = ((const float4*)(A + (size_t)(row0 + r) * lda))[c4];
    }
    __syncthreads();

    float acc[ROWS];
#pragma unroll
    for (int r = 0; r < ROWS; r++) acc[r] = 0.f;

#pragma unroll 8
    for (int k = 0; k < K; k++) {
        float w = W[(size_t)k * N + col];
#pragma unroll
        for (int r = 0; r < ROWS; r++)
            acc[r] = fmaf(As[r][k], w, acc[r]);
    }

    const float bb = bias[col];
#pragma unroll
    for (int r = 0; r < ROWS; r++)
        C[(size_t)(row0 + r) * N + col] = acc[r] + bb;
}

// ---------------------------------------------------------------------------
// LSTM scan + piggybacked keys-GEMM.
// Blocks 0..7: LSTM scan for batch b (sequential over t, 8 SMs busy).
// Blocks 8..263: keys = attended @ W1 + b1 on the otherwise-idle SMs,
//                overlapping the scan (keys consumed only by attn).
// ---------------------------------------------------------------------------
__global__ __launch_bounds__(256, 1)
void lstm_keys_kernel(const float* __restrict__ xz,
                      const float* __restrict__ Wr,       // (128, 512)
                      float* __restrict__ out,
                      const float* __restrict__ attended, // (8,512,128)
                      const float* __restrict__ W1,       // (128,128)
                      const float* __restrict__ b1,       // (128,)
                      float* __restrict__ keys)           // (8,512,128)
{
    extern __shared__ u64 smraw[];
    const int j = threadIdx.x;     // 0..255

    if (blockIdx.x >= B_) {
        // ---------------- keys-GEMM block ----------------
        // 16 rows x 128 cols per block; thread: col = j&127, 8 rows
        float* As = (float*)smraw;              // [16][128] floats, 8KB
        const int row0  = (blockIdx.x - B_) * KEYS_ROWS;
        const int col   = j & 127;
        const int rbase = (j >> 7) * 8;         // 0 or 8

        for (int i = j; i < KEYS_ROWS * 32; i += 256) {
            int r = i >> 5, c4 = i & 31;
            ((float4*)&As[r * 128])[c4] =
                ((const float4*)(attended + (size_t)(row0 + r) * 128))[c4];
        }
        __syncthreads();

        float acc[8];
#pragma unroll
        for (int r = 0; r < 8; r++) acc[r] = 0.f;
#pragma unroll 8
        for (int k = 0; k < 128; k++) {
            float w = W1[k * 128 + col];
#pragma unroll
            for (int r = 0; r < 8; r++)
                acc[r] = fmaf(As[(rbase + r) * 128 + k], w, acc[r]);
        }
        const float bb = b1[col];
#pragma unroll
        for (int r = 0; r < 8; r++)
            keys[(size_t)(row0 + rbase + r) * 128 + col] = acc[r] + bb;
        return;
    }

    // ---------------- LSTM block ----------------
    // Thread j owns gate columns j and j+256 (K-packed FFMA2, 2 MACs/instr).
    //  - Wr rows 0..95: registers (48 k-pairs x 2 cols = 192 regs/thread)
    //  - Wr rows 96..127: SMEM ulonglong2 (4 rows/LDS.128), conflict-free
    //  - gate split: thread j>=128 computes SIGMOIDS of (z_f, z_o) before the
    //    barrier (shortens the j<128 serial tail); thread j<128 keeps z_i,
    //    z_g in registers.
    //  - tail tanh via __expf (tanh_e): short serial chain, rel err ~1e-6
    ulonglong2* wsp2 = (ulonglong2*)smraw;            // [SCHUNK][512]
    float*  h_s   = (float*)(wsp2 + SCHUNK * 512);    // [128], 16B aligned
    float2* zfo_s = (float2*)(h_s + 128);             // [128] (sig f, sig o)

    const int b = blockIdx.x;

    // Register weights: k-pairs for rows 0..95, columns j and j+256
    u64 w0[RPAIRS], w1r[RPAIRS];
#pragma unroll
    for (int p = 0; p < RPAIRS; p++) {
        w0[p]  = pack2(Wr[(2 * p) * 512 + j],       Wr[(2 * p + 1) * 512 + j]);
        w1r[p] = pack2(Wr[(2 * p) * 512 + j + 256], Wr[(2 * p + 1) * 512 + j + 256]);
    }

    // SMEM weights rows 96..127: chunk q covers rows 96+4q .. 96+4q+3
    for (int i = j; i < SCHUNK * 512; i += 256) {
        int q = i >> 9, col = i & 511;
        int r0 = 96 + 4 * q;
        ulonglong2 v;
        v.x = pack2(Wr[(r0 + 0) * 512 + col], Wr[(r0 + 1) * 512 + col]);
        v.y = pack2(Wr[(r0 + 2) * 512 + col], Wr[(r0 + 3) * 512 + col]);
        wsp2[q * 512 + col] = v;
    }

    float c = 0.f;
    if (j < L_) h_s[j] = 0.f;
    __syncthreads();

    const float* xzb = xz + (size_t)b * TOUT * 512;

    float x0 = xzb[j];
    float x1 = xzb[j + 256];

    for (int t = 0; t < TOUT; t++) {
        u64 a0 = pack2(x0, 0.f);   // col j accumulator (even-k lo, odd-k hi)
        u64 a1 = 0ull;
        u64 a2 = pack2(x1, 0.f);   // col j+256 accumulator
        u64 a3 = 0ull;

        // prefetch next step's xz (independent of the FMA chain below)
        float x0n = 0.f, x1n = 0.f;
        if (t + 1 < TOUT) {
            x0n = xzb[(t + 1) * 512 + j];
            x1n = xzb[(t + 1) * 512 + j + 256];
        }

        // rows 0..95: register weights; 1 broadcast LDS.128 -> 4 rows x 2 cols
#pragma unroll
        for (int i = 0; i < RPAIRS / 2; i++) {          // i = 0..23
            ulonglong2 hp = *(const ulonglong2*)&h_s[4 * i];
            a0 = ffma2(hp.x, w0[2 * i],      a0);
            a1 = ffma2(hp.y, w0[2 * i + 1],  a1);
            a2 = ffma2(hp.x, w1r[2 * i],     a2);
            a3 = ffma2(hp.y, w1r[2 * i + 1], a3);
        }
        // rows 96..127: SMEM weights (LDS.128, 16B stride across threads)
#pragma unroll
        for (int q = 0; q < SCHUNK; q++) {
            ulonglong2 hp = *(const ulonglong2*)&h_s[96 + 4 * q];
            ulonglong2 wa = wsp2[q * 512 + j];
            ulonglong2 wb = wsp2[q * 512 + j + 256];
            a0 = ffma2(hp.x, wa.x, a0);
            a1 = ffma2(hp.y, wa.y, a1);
            a2 = ffma2(hp.x, wb.x, a2);
            a3 = ffma2(hp.y, wb.y, a3);
        }
        float2 f0 = unpack2(add2(a0, a1));   // z[col j]
        float2 f1 = unpack2(add2(a2, a3));   // z[col j+256]
        const float zA = f0.x + f0.y;        // j<128: z_i ; j>=128: z_f
        const float zB = f1.x + f1.y;        // j<128: z_g ; j>=128: z_o

        // producer half applies sigmoid BEFORE the barrier -> shorter consumer tail
        if (j >= 128)
            zfo_s[j - 128] = make_float2(sigmoidf_(zA), sigmoidf_(zB));
        __syncthreads();

        if (j < L_) {
            const float2 fo = zfo_s[j];      // (sigmoid(z_f), sigmoid(z_o))
            const float ig = sigmoidf_(zA);  // independent of tanh_e(zB) below
            const float gg = tanh_e(zB);
            c = fmaf(fo.x, c, ig * gg);
            const float hn = fo.y * tanh_e(c);
            h_s[j] = hn;
            out[((size_t)(b * TOUT + t)) * 256 + j] = hn;
        }
        __syncthreads();

        x0 = x0n;
        x1 = x1n;
    }

    if (j < L_) {
        out[OUT_H_OFF + b * L_ + j] = h_s[j];
        out[OUT_C_OFF + b * L_ + j] = c;
    }
}

// ---------------------------------------------------------------------------
// Fused q-projection + Bahdanau attention:
//   q = x @ W2 + b2 (W2 staged in SMEM, warp w computes its own q-row)
//   scores = tanh(keys + q) . W3 -> softmax -> @ att
// Block = (b, 8 q-rows), 256 threads. p_s aliases the W2 SMEM region after
// the q phase. Phase 1 reduces TWO scores per butterfly round (3 shfl/k
// instead of 5). Never materializes the (8,256,512,128) tensor.
// ---------------------------------------------------------------------------
__global__ __launch_bounds__(256)
void attn_kernel(const float* __restrict__ keys,   // (8,512,128)
                 const float* __restrict__ W2,     // (128,128)
                 const float* __restrict__ b2,     // (128,)
                 const float* __restrict__ att,    // (8,512,128)
                 const float* __restrict__ W3,     // (128,)
                 float* __restrict__ out)          // x read from [...,0:128]
{
    extern __shared__ float smf[];
    float* w2s = smf;                       // [128][128] floats (64KB)
    float* ps  = smf;                       // [8][512] ALIAS (after q phase)
    float* qs  = smf + 16384;               // [8][128]
    float* xs  = qs + 1024;                 // [8][128]
    float* w3s = xs + 1024;                 // [128]
    float* b2s = w3s + 128;                 // [128]

    const int b    = blockIdx.y;
    const int q0   = blockIdx.x * 8;
    const int tid  = threadIdx.x;
    const int warp = tid >> 5;
    const int lane = tid & 31;

    // ---- Stage W2, x rows, w3, b2
    for (int i = tid; i < 128 * 32; i += 256)           // 4096 float4
        ((float4*)w2s)[i] = ((const float4*)W2)[i];
    for (int i = tid; i < 8 * 32; i += 256) {           // x: 8 rows x 128
        int r = i >> 5, c4 = i & 31;
        ((float4*)&xs[r * 128])[c4] =
            *(const float4*)(out + ((size_t)(b * TOUT + q0 + r)) * 256 + c4 * 4);
    }
    if (tid < 128) { w3s[tid] = W3[tid]; b2s[tid] = b2[tid]; }
    __syncthreads();

    // ---- q phase: warp w computes q row w; lane handles cols 4l..4l+3
    {
        const int r = warp;
        float4 acc = *(const float4*)&b2s[lane * 4];
        const float* xr = &xs[r * 128];
#pragma unroll 4
        for (int k = 0; k < 128; k++) {
            float xv = xr[k];
            float4 wv = *(const float4*)&w2s[k * 128 + lane * 4];
            acc.x = fmaf(xv, wv.x, acc.x);
            acc.y = fmaf(xv, wv.y, acc.y);
            acc.z = fmaf(xv, wv.z, acc.z);
            acc.w = fmaf(xv, wv.w, acc.w);
        }
        *(float4*)&qs[r * 128 + lane * 4] = acc;
    }
    __syncthreads();   // all q done before ps (aliasing w2s) is written

    const float* keysb = keys + (size_t)b * TIN * L_;
    const float* attb  = att  + (size_t)b * TIN * L_;

    // ---- Phase 1: scores, two k's per reduction round.
    // After s += shfl_xor(s,16), lanes<16 hold s0-partials and lanes>=16 hold
    // s1-partials; 4 shared butterflies finish both. Lane 0 -> k, lane 16 -> k+1.
    {
        const int r = warp;
        const float4 qv = *(const float4*)&qs[r * 128 + lane * 4];
        const float4 wv = *(const float4*)&w3s[lane * 4];
        for (int k = 0; k < TIN; k += 2) {
            float4 k0 = *(const float4*)(keysb + (size_t)k * L_ + lane * 4);
            float4 k1 = *(const float4*)(keysb + (size_t)(k + 1) * L_ + lane * 4);
            float s0, s1;
            s0 = tanh_fast(k0.x + qv.x) * wv.x;
            s0 = fmaf(tanh_fast(k0.y + qv.y), wv.y, s0);
            s0 = fmaf(tanh_fast(k0.z + qv.z), wv.z, s0);
            s0 = fmaf(tanh_fast(k0.w + qv.w), wv.w, s0);
            s1 = tanh_fast(k1.x + qv.x) * wv.x;
            s1 = fmaf(tanh_fast(k1.y + qv.y), wv.y, s1);
            s1 = fmaf(tanh_fast(k1.z + qv.z), wv.z, s1);
            s1 = fmaf(tanh_fast(k1.w + qv.w), wv.w, s1);
            s0 += __shfl_xor_sync(0xffffffffu, s0, 16);
            s1 += __shfl_xor_sync(0xffffffffu, s1, 16);
            float sc = (lane < 16) ? s0 : s1;
#pragma unroll
            for (int o = 8; o; o >>= 1)
                sc += __shfl_xor_sync(0xffffffffu, sc, o);
            if (lane == 0)  ps[r * TIN + k] = sc;       // b3 shift-invariant
            if (lane == 16) ps[r * TIN + k + 1] = sc;
        }
    }
    __syncthreads();

    // ---- Phase 2: softmax per q-row (warp-parallel over k)
    {
        const int r = warp;
        float mx = -1e30f;
        for (int k = lane; k < TIN; k += 32) mx = fmaxf(mx, ps[r * TIN + k]);
#pragma unroll
        for (int o = 16; o; o >>= 1)
            mx = fmaxf(mx, __shfl_xor_sync(0xffffffffu, mx, o));
        float sum = 0.f;
        for (int k = lane; k < TIN; k += 32) {
            float e = __expf(ps[r * TIN + k] - mx);
            ps[r * TIN + k] = e;
            sum += e;
        }
#pragma unroll
        for (int o = 16; o; o >>= 1)
            sum += __shfl_xor_sync(0xffffffffu, sum, o);
        float inv = 1.0f / sum;
        for (int k = lane; k < TIN; k += 32) ps[r * TIN + k] *= inv;
    }
    __syncthreads();

    // ---- Phase 3: weighted = attn @ att. warp w -> q-row w, lane owns 4 d's
    {
        const int r = warp;
        float4 acc = make_float4(0.f, 0.f, 0.f, 0.f);
#pragma unroll 2
        for (int k = 0; k < TIN; k++) {
            float  p = ps[r * TIN + k];
            float4 a = *(const float4*)(attb + (size_t)k * L_ + lane * 4);
            acc.x = fmaf(p, a.x, acc.x);
            acc.y = fmaf(p, a.y, acc.y);
            acc.z = fmaf(p, a.z, acc.z);
            acc.w = fmaf(p, a.w, acc.w);
        }
        float* op = out + ((size_t)(b * TOUT + q0 + r)) * 256 + 128 + lane * 4;
        *(float4*)op = acc;
    }
}

// ---------------------------------------------------------------------------
extern "C" void kernel_launch(void* const* d_in, const int* in_sizes, int n_in,
                              void* d_out, int out_size)
{
    const float* inputs   = (const float*)d_in[0];   // (8,256,128)
    const float* attended = (const float*)d_in[1];   // (8,512,128)
    const float* lstm_k   = (const float*)d_in[2];   // (128,512)
    const float* lstm_rk  = (const float*)d_in[3];   // (128,512)
    const float* lstm_b   = (const float*)d_in[4];   // (512,)
    const float* W1       = (const float*)d_in[5];   // (128,128)
    const float* b1       = (const float*)d_in[6];   // (128,)
    const float* W2       = (const float*)d_in[7];   // (128,128)
    const float* b2       = (const float*)d_in[8];   // (128,)
    const float* W3       = (const float*)d_in[9];   // (128,1)
    // d_in[10] = b3: shift-invariant under softmax, unused

    float* out = (float*)d_out;

    float* keys; cudaGetSymbolAddress((void**)&keys, g_keys);
    float* xz;   cudaGetSymbolAddress((void**)&xz,   g_xz);

    // Opt-in to >48KB dynamic SMEM (configuration, not allocation)
    cudaFuncSetAttribute(lstm_keys_kernel,
                         cudaFuncAttributeMaxDynamicSharedMemorySize,
                         LSTM_DYN_SMEM);
    cudaFuncSetAttribute(attn_kernel,
                         cudaFuncAttributeMaxDynamicSharedMemorySize,
                         ATTN_DYN_SMEM);

    // xz = inputs @ lstm_kernel + lstm_bias : M=2048, N=512 -> 1024 blocks
    {
        dim3 grid(B_ * TOUT / 8, 4);
        gemm_bias_kernel<<<grid, 128>>>(inputs, 128, lstm_k, lstm_b, xz, 512);
    }
    // LSTM scan (blocks 0..7) + keys GEMM (blocks 8..263) overlapped.
    // Writes x into out[...,0:128], h,c tail, and g_keys.
    lstm_keys_kernel<<<B_ + KEYS_BLOCKS, 256, LSTM_DYN_SMEM>>>(
        xz, lstm_rk, out, attended, W1, b1, keys);

    // fused q-projection + scores -> softmax -> weighted, writes out[...,128:256]
    {
        dim3 grid(TOUT / 8, B_);
        attn_kernel<<<grid, 256, ATTN_DYN_SMEM>>>(keys, W2, b2, attended, W3, out);
    }
}